// round 1
// baseline (speedup 1.0000x reference)
#include <cuda_runtime.h>
#include <math.h>

// Problem dims
#define BB 2
#define DD 128
#define HH 128
#define WW 128
#define CW 0.1f
#define TWO_PI 6.283185307179586f

// Channels-last scratch buffers (allowed: __device__ globals, not cudaMalloc)
__device__ float g_s1[(size_t)BB * DD * HH * WW * 8];    // conv1 output, [b][d][h][w][8]
__device__ float g_s2[(size_t)BB * DD * HH * WW * 16];   // conv2 output, [b][d][h][w][16]

// ---------------------------------------------------------------------------
// Kernel 1: field modulation + conv3d(1->8) + ReLU
// block (8,8,8) = 512 threads, each thread one voxel, 8 output channels
// ---------------------------------------------------------------------------
__global__ __launch_bounds__(512, 2)
void k_conv1(const float* __restrict__ x,
             const float* __restrict__ w1,
             const float* __restrict__ b1)
{
    __shared__ float tile[10 * 10 * 10];   // field-premultiplied input, halo 1
    __shared__ float wk[27 * 8];           // [tap][co]
    __shared__ float bs[8];

    const int tx = threadIdx.x, ty = threadIdx.y, tz = threadIdx.z;
    const int tid = (tz * 8 + ty) * 8 + tx;
    const int b  = blockIdx.z >> 4;
    const int z0 = (blockIdx.z & 15) << 3;
    const int y0 = blockIdx.y << 3;
    const int x0 = blockIdx.x << 3;

    // stage weights: wk[tap*8+co] = w1[co*27+tap]
    if (tid < 216) {
        int tap = tid >> 3, co = tid & 7;
        wk[tid] = w1[co * 27 + tap];
    }
    if (tid < 8) bs[tid] = b1[tid];

    // stage input tile with field factor applied
    const float inv = TWO_PI / (float)(DD + HH + WW);
    for (int idx = tid; idx < 1000; idx += 512) {
        int lz = idx / 100, r = idx % 100, ly = r / 10, lx = r % 10;
        int gz = z0 - 1 + lz, gy = y0 - 1 + ly, gx = x0 - 1 + lx;
        float v = 0.0f;
        if (gz >= 0 && gz < DD && gy >= 0 && gy < HH && gx >= 0 && gx < WW) {
            v = x[(((size_t)b * DD + gz) * HH + gy) * WW + gx];
            float s = (float)(gz + gy + gx);
            v *= 1.0f + CW * sinf(inv * s);
        }
        tile[idx] = v;
    }
    __syncthreads();

    float acc[8];
#pragma unroll
    for (int c = 0; c < 8; c++) acc[c] = bs[c];

#pragma unroll
    for (int kz = 0; kz < 3; kz++)
#pragma unroll
        for (int ky = 0; ky < 3; ky++)
#pragma unroll
            for (int kx = 0; kx < 3; kx++) {
                float v = tile[((tz + kz) * 10 + (ty + ky)) * 10 + (tx + kx)];
                int tap = (kz * 3 + ky) * 3 + kx;
                float4 wa = *(const float4*)&wk[tap * 8];
                float4 wb = *(const float4*)&wk[tap * 8 + 4];
                acc[0] = fmaf(v, wa.x, acc[0]);
                acc[1] = fmaf(v, wa.y, acc[1]);
                acc[2] = fmaf(v, wa.z, acc[2]);
                acc[3] = fmaf(v, wa.w, acc[3]);
                acc[4] = fmaf(v, wb.x, acc[4]);
                acc[5] = fmaf(v, wb.y, acc[5]);
                acc[6] = fmaf(v, wb.z, acc[6]);
                acc[7] = fmaf(v, wb.w, acc[7]);
            }

    const int gz = z0 + tz, gy = y0 + ty, gx = x0 + tx;
    size_t out = ((((size_t)b * DD + gz) * HH + gy) * WW + gx) * 8;
#pragma unroll
    for (int c = 0; c < 8; c++) acc[c] = fmaxf(acc[c], 0.0f);
    *(float4*)&g_s1[out]     = make_float4(acc[0], acc[1], acc[2], acc[3]);
    *(float4*)&g_s1[out + 4] = make_float4(acc[4], acc[5], acc[6], acc[7]);
}

// ---------------------------------------------------------------------------
// Kernel 2: conv3d(8->16) + ReLU   (the FFMA-bound core: 3456 FMA/voxel)
// ---------------------------------------------------------------------------
__global__ __launch_bounds__(512, 2)
void k_conv2(const float* __restrict__ w2,
             const float* __restrict__ b2)
{
    __shared__ float tile[10 * 10 * 10 * 8];   // 32 KB, [pos][ci]
    __shared__ float ws[27 * 8 * 16];          // 13.8 KB, [tap][ci][co]
    __shared__ float bs[16];

    const int tx = threadIdx.x, ty = threadIdx.y, tz = threadIdx.z;
    const int tid = (tz * 8 + ty) * 8 + tx;
    const int b  = blockIdx.z >> 4;
    const int z0 = (blockIdx.z & 15) << 3;
    const int y0 = blockIdx.y << 3;
    const int x0 = blockIdx.x << 3;

    // ws[(tap*8+ci)*16+co] = w2[(co*8+ci)*27+tap]
    for (int i = tid; i < 3456; i += 512) {
        int tap = i >> 7, r = i & 127, ci = r >> 4, co = r & 15;
        ws[i] = w2[(co * 8 + ci) * 27 + tap];
    }
    if (tid < 16) bs[tid] = b2[tid];

    for (int idx = tid; idx < 1000; idx += 512) {
        int lz = idx / 100, r = idx % 100, ly = r / 10, lx = r % 10;
        int gz = z0 - 1 + lz, gy = y0 - 1 + ly, gx = x0 - 1 + lx;
        float4 a = make_float4(0.f, 0.f, 0.f, 0.f), c = a;
        if (gz >= 0 && gz < DD && gy >= 0 && gy < HH && gx >= 0 && gx < WW) {
            size_t base = ((((size_t)b * DD + gz) * HH + gy) * WW + gx) * 8;
            a = *(const float4*)&g_s1[base];
            c = *(const float4*)&g_s1[base + 4];
        }
        *(float4*)&tile[idx * 8]     = a;
        *(float4*)&tile[idx * 8 + 4] = c;
    }
    __syncthreads();

    float acc[16];
#pragma unroll
    for (int c = 0; c < 16; c++) acc[c] = bs[c];

#pragma unroll
    for (int kz = 0; kz < 3; kz++)
#pragma unroll
        for (int ky = 0; ky < 3; ky++)
#pragma unroll
            for (int kx = 0; kx < 3; kx++) {
                const int tap = (kz * 3 + ky) * 3 + kx;
                const float* ip = &tile[(((tz + kz) * 10 + (ty + ky)) * 10 + (tx + kx)) * 8];
                float4 i0 = *(const float4*)ip;
                float4 i1 = *(const float4*)(ip + 4);
                float in8[8] = {i0.x, i0.y, i0.z, i0.w, i1.x, i1.y, i1.z, i1.w};
                const float* wb = &ws[tap * 128];
#pragma unroll
                for (int ci = 0; ci < 8; ci++) {
                    float v = in8[ci];
#pragma unroll
                    for (int q = 0; q < 4; q++) {
                        float4 wv = *(const float4*)&wb[ci * 16 + q * 4];
                        acc[q * 4 + 0] = fmaf(v, wv.x, acc[q * 4 + 0]);
                        acc[q * 4 + 1] = fmaf(v, wv.y, acc[q * 4 + 1]);
                        acc[q * 4 + 2] = fmaf(v, wv.z, acc[q * 4 + 2]);
                        acc[q * 4 + 3] = fmaf(v, wv.w, acc[q * 4 + 3]);
                    }
                }
            }

    const int gz = z0 + tz, gy = y0 + ty, gx = x0 + tx;
    size_t out = ((((size_t)b * DD + gz) * HH + gy) * WW + gx) * 16;
#pragma unroll
    for (int c = 0; c < 16; c++) acc[c] = fmaxf(acc[c], 0.0f);
#pragma unroll
    for (int q = 0; q < 4; q++)
        *(float4*)&g_s2[out + q * 4] =
            make_float4(acc[q * 4], acc[q * 4 + 1], acc[q * 4 + 2], acc[q * 4 + 3]);
}

// ---------------------------------------------------------------------------
// Kernel 3: conv3d(16->1) + tanh
// dynamic smem tile: 10^3 * 16 floats = 64 KB
// ---------------------------------------------------------------------------
extern __shared__ float dyn_tile[];

__global__ __launch_bounds__(512, 2)
void k_conv3(const float* __restrict__ w3,
             const float* __restrict__ b3,
             float* __restrict__ out)
{
    __shared__ float ws[27 * 16];  // [tap][ci]
    __shared__ float bsv;

    const int tx = threadIdx.x, ty = threadIdx.y, tz = threadIdx.z;
    const int tid = (tz * 8 + ty) * 8 + tx;
    const int b  = blockIdx.z >> 4;
    const int z0 = (blockIdx.z & 15) << 3;
    const int y0 = blockIdx.y << 3;
    const int x0 = blockIdx.x << 3;

    if (tid < 432) {
        int tap = tid >> 4, ci = tid & 15;
        ws[tid] = w3[ci * 27 + tap];
    }
    if (tid == 0) bsv = b3[0];

    // 1000 positions * 4 float4
    for (int idx = tid; idx < 4000; idx += 512) {
        int pos = idx >> 2, q = idx & 3;
        int lz = pos / 100, r = pos % 100, ly = r / 10, lx = r % 10;
        int gz = z0 - 1 + lz, gy = y0 - 1 + ly, gx = x0 - 1 + lx;
        float4 v = make_float4(0.f, 0.f, 0.f, 0.f);
        if (gz >= 0 && gz < DD && gy >= 0 && gy < HH && gx >= 0 && gx < WW) {
            size_t base = ((((size_t)b * DD + gz) * HH + gy) * WW + gx) * 16;
            v = *(const float4*)&g_s2[base + q * 4];
        }
        *(float4*)&dyn_tile[pos * 16 + q * 4] = v;
    }
    __syncthreads();

    float acc = bsv;
#pragma unroll
    for (int kz = 0; kz < 3; kz++)
#pragma unroll
        for (int ky = 0; ky < 3; ky++)
#pragma unroll
            for (int kx = 0; kx < 3; kx++) {
                const int tap = (kz * 3 + ky) * 3 + kx;
                const float* ip = &dyn_tile[(((tz + kz) * 10 + (ty + ky)) * 10 + (tx + kx)) * 16];
                const float* wb = &ws[tap * 16];
#pragma unroll
                for (int q = 0; q < 4; q++) {
                    float4 iv = *(const float4*)&ip[q * 4];
                    float4 wv = *(const float4*)&wb[q * 4];
                    acc = fmaf(iv.x, wv.x, acc);
                    acc = fmaf(iv.y, wv.y, acc);
                    acc = fmaf(iv.z, wv.z, acc);
                    acc = fmaf(iv.w, wv.w, acc);
                }
            }

    const int gz = z0 + tz, gy = y0 + ty, gx = x0 + tx;
    out[(((size_t)b * DD + gz) * HH + gy) * WW + gx] = tanhf(acc);
}

// ---------------------------------------------------------------------------
extern "C" void kernel_launch(void* const* d_in, const int* in_sizes, int n_in,
                              void* d_out, int out_size)
{
    const float* x  = (const float*)d_in[0];
    const float* w1 = (const float*)d_in[1];
    const float* b1 = (const float*)d_in[2];
    const float* w2 = (const float*)d_in[3];
    const float* b2 = (const float*)d_in[4];
    const float* w3 = (const float*)d_in[5];
    const float* b3 = (const float*)d_in[6];
    float* out = (float*)d_out;

    static bool attr_set = false;  // idempotent attribute set (not a work guard)
    if (!attr_set) {
        cudaFuncSetAttribute(k_conv3, cudaFuncAttributeMaxDynamicSharedMemorySize,
                             10 * 10 * 10 * 16 * sizeof(float));
        attr_set = true;
    }

    dim3 blk(8, 8, 8);
    dim3 grd(WW / 8, HH / 8, (DD / 8) * BB);

    k_conv1<<<grd, blk>>>(x, w1, b1);
    k_conv2<<<grd, blk>>>(w2, b2);
    k_conv3<<<grd, blk, 10 * 10 * 10 * 16 * sizeof(float)>>>(w3, b3, out);
}